// round 8
// baseline (speedup 1.0000x reference)
#include <cuda_runtime.h>
#include <cstdint>

#define N_ROWS   131072
#define K_CODES  512
#define D_DIM    64
#define ZQ_ELEMS (N_ROWS * D_DIM)
#define TILE_M   128
#define NTILES   (N_ROWS / TILE_M)
#define THREADS  256
#define GRID     152

// smem float offsets
#define O_BF   0          // 64nt * 512 words fragment-packed B (128KB)
#define O_Z    32768      // 128*65
#define O_NRM  41088      // 512
#define O_ZN   41600      // 128
#define O_WIN  41728      // 128 int
#define O_LSTF 41856      // 128 int
#define O_CNT  41984      // 1 int
#define O_C    41985      // 1 float (eps slope)
#define SMEM_F 41988
#define SMEM_BYTES (SMEM_F * 4)

__device__ __forceinline__ uint32_t f2tf32(float f) {
    uint32_t r;
    asm("cvt.rna.tf32.f32 %0, %1;" : "=r"(r) : "f"(f));
    return r;
}
__device__ __forceinline__ void mma_tf32(float& c0, float& c1, float& c2, float& c3,
                                         uint32_t a0, uint32_t a1, uint32_t a2, uint32_t a3,
                                         uint32_t b0, uint32_t b1) {
    asm volatile(
        "mma.sync.aligned.m16n8k8.row.col.f32.tf32.tf32.f32 "
        "{%0,%1,%2,%3}, {%4,%5,%6,%7}, {%8,%9}, {%0,%1,%2,%3};"
        : "+f"(c0), "+f"(c1), "+f"(c2), "+f"(c3)
        : "r"(a0), "r"(a1), "r"(a2), "r"(a3), "r"(b0), "r"(b1));
}

// light 2-tracker update: strict < keeps first (lowest-k) min
#define UPD(m1, m2, k1, u, n) \
    { bool p_ = (u) < (m1); (m2) = p_ ? (m1) : fminf((m2), (u)); \
      (k1) = p_ ? (n) : (k1); (m1) = p_ ? (u) : (m1); }

__device__ __forceinline__ void mrg2(float& m1, float& m2, int& k1, int off) {
    float b1 = __shfl_xor_sync(0xffffffffu, m1, off);
    float b2 = __shfl_xor_sync(0xffffffffu, m2, off);
    int  bk1 = __shfl_xor_sync(0xffffffffu, k1, off);
    float nm2 = fminf(fmaxf(m1, b1), fminf(m2, b2));
    if (b1 < m1 || (b1 == m1 && bk1 < k1)) { m1 = b1; k1 = bk1; }
    m2 = nm2;
}

__global__ void __launch_bounds__(THREADS, 1)
vq_mma(const float* __restrict__ z_e, const float* __restrict__ cb,
       float* __restrict__ out, float* __restrict__ fidx) {
    extern __shared__ float sh[];
    float* sBF  = sh + O_BF;
    float* sZ   = sh + O_Z;
    float* sNrm = sh + O_NRM;
    float* sZn  = sh + O_ZN;
    int*   sWin = (int*)(sh + O_WIN);
    int*   sLF  = (int*)(sh + O_LSTF);
    int*   sCnt = (int*)(sh + O_CNT);
    float* sC   = sh + O_C;

    const int tid = threadIdx.x, wid = tid >> 5, lid = tid & 31;
    const int qid = lid & 3, gid = lid >> 2;

    // ---- one-time: pack B fragments, chunked conflict-free layout ----
    // BF4[nt*128 + c*32 + lane] = { cb[k][d(j)] : j = c*4+u }, j=2ks+h,
    // d = ks*8 + qid + h*4, k = nt*8 + gid   (verified in R7, rel_err 0)
    {
        float4* bf4 = (float4*)sBF;
        for (int e = tid; e < 8192; e += THREADS) {
            int nt = e >> 7, rem = e & 127;
            int c = rem >> 5, l = rem & 31;
            int g = l >> 2, q = l & 3;
            const float* ck = cb + (nt * 8 + g) * D_DIM;
            int j0 = c * 4;
            float4 v;
            v.x = ck[((j0 + 0) >> 1) * 8 + q + ((j0 + 0) & 1) * 4];
            v.y = ck[((j0 + 1) >> 1) * 8 + q + ((j0 + 1) & 1) * 4];
            v.z = ck[((j0 + 2) >> 1) * 8 + q + ((j0 + 2) & 1) * 4];
            v.w = ck[((j0 + 3) >> 1) * 8 + q + ((j0 + 3) & 1) * 4];
            bf4[e] = v;
        }
    }
    for (int k = tid; k < K_CODES; k += THREADS) {   // sequential-d norms
        const float* e = cb + k * D_DIM;
        float s = 0.0f;
#pragma unroll 8
        for (int d = 0; d < D_DIM; d++)
            s = __fadd_rn(s, __fmul_rn(e[d], e[d]));
        sNrm[k] = s;
    }
    __syncthreads();
    if (tid == 0) {   // eps slope ~ 4*(2^-10+2^-11)*||e||max, + margin
        float mx = 0.0f;
        for (int k = 0; k < K_CODES; k++) mx = fmaxf(mx, sNrm[k]);
        *sC = 6.0e-3f * sqrtf(mx);
    }
    __syncthreads();

    for (int tile = blockIdx.x; tile < NTILES; tile += GRID) {
        __syncthreads();
        {   // stage z tile -> sZ[row][c] (pad 65)
            const int row0 = tile * TILE_M;
            const float4* z4 = (const float4*)(z_e + (long)(row0 >> 12) * 262144
                                               + (row0 & 4095));
#pragma unroll
            for (int m = 0; m < 8; m++) {
                int q = tid + THREADS * m;
                int c = q >> 5, i4 = q & 31;
                float4 v = z4[c * 1024 + i4];
                int r = i4 * 4;
                sZ[(r + 0) * 65 + c] = v.x;
                sZ[(r + 1) * 65 + c] = v.y;
                sZ[(r + 2) * 65 + c] = v.z;
                sZ[(r + 3) * 65 + c] = v.w;
            }
        }
        if (tid == 0) sCnt[0] = 0;
        __syncthreads();
        if (tid < TILE_M) {
            const float* zr = sZ + tid * 65;
            float s = 0.0f;
#pragma unroll 8
            for (int d = 0; d < D_DIM; d++)
                s = __fadd_rn(s, __fmul_rn(zr[d], zr[d]));
            sZn[tid] = s;
        }
        __syncthreads();

        // ---- mma + fused argmin: warp covers 16 rows x 512 codes ----
        {
            const int rb = wid * 16;
            uint32_t A[8][4];
#pragma unroll
            for (int ks = 0; ks < 8; ks++) {
                const float* r0 = sZ + (rb + gid) * 65 + ks * 8 + qid;
                const float* r1 = r0 + 8 * 65;
                A[ks][0] = f2tf32(r0[0]);
                A[ks][1] = f2tf32(r1[0]);
                A[ks][2] = f2tf32(r0[4]);
                A[ks][3] = f2tf32(r1[4]);
            }
            float A1 = 3.4e38f, A2 = 3.4e38f, B1 = 3.4e38f, B2 = 3.4e38f;
            int Ak1 = 0, Bk1 = 0;
            const float2* nrm2 = (const float2*)sNrm;
            const float4* bf4 = (const float4*)sBF;
            float4 w0 = bf4[lid], w1 = bf4[32 + lid];
            float4 w2 = bf4[64 + lid], w3 = bf4[96 + lid];
#pragma unroll 1
            for (int nt = 0; nt < 64; nt++) {
                // prefetch next nt's fragments (wraps harmlessly at 63)
                const int bb = ((nt + 1) & 63) * 128 + lid;
                float4 v0 = bf4[bb], v1 = bf4[bb + 32];
                float4 v2 = bf4[bb + 64], v3 = bf4[bb + 96];
                // 4 independent 2-deep MMA chains
                float p0 = 0, p1 = 0, p2 = 0, p3 = 0;
                float q0 = 0, q1 = 0, q2 = 0, q3 = 0;
                float r0 = 0, r1 = 0, r2 = 0, r3 = 0;
                float s0 = 0, s1 = 0, s2 = 0, s3 = 0;
                mma_tf32(p0, p1, p2, p3, A[0][0], A[0][1], A[0][2], A[0][3],
                         __float_as_uint(w0.x), __float_as_uint(w0.y));
                mma_tf32(q0, q1, q2, q3, A[2][0], A[2][1], A[2][2], A[2][3],
                         __float_as_uint(w1.x), __float_as_uint(w1.y));
                mma_tf32(r0, r1, r2, r3, A[4][0], A[4][1], A[4][2], A[4][3],
                         __float_as_uint(w2.x), __float_as_uint(w2.y));
                mma_tf32(s0, s1, s2, s3, A[6][0], A[6][1], A[6][2], A[6][3],
                         __float_as_uint(w3.x), __float_as_uint(w3.y));
                mma_tf32(p0, p1, p2, p3, A[1][0], A[1][1], A[1][2], A[1][3],
                         __float_as_uint(w0.z), __float_as_uint(w0.w));
                mma_tf32(q0, q1, q2, q3, A[3][0], A[3][1], A[3][2], A[3][3],
                         __float_as_uint(w1.z), __float_as_uint(w1.w));
                mma_tf32(r0, r1, r2, r3, A[5][0], A[5][1], A[5][2], A[5][3],
                         __float_as_uint(w2.z), __float_as_uint(w2.w));
                mma_tf32(s0, s1, s2, s3, A[7][0], A[7][1], A[7][2], A[7][3],
                         __float_as_uint(w3.z), __float_as_uint(w3.w));
                float t0 = (p0 + q0) + (r0 + s0);
                float t1 = (p1 + q1) + (r1 + s1);
                float t2 = (p2 + q2) + (r2 + s2);
                float t3 = (p3 + q3) + (r3 + s3);
                float2 nk = nrm2[nt * 4 + qid];
                int n0 = nt * 8 + 2 * qid;
                float u0 = __fmaf_rn(-2.0f, t0, nk.x);
                float u1 = __fmaf_rn(-2.0f, t1, nk.y);
                float u2 = __fmaf_rn(-2.0f, t2, nk.x);
                float u3 = __fmaf_rn(-2.0f, t3, nk.y);
                UPD(A1, A2, Ak1, u0, n0);
                UPD(A1, A2, Ak1, u1, n0 + 1);
                UPD(B1, B2, Bk1, u2, n0);
                UPD(B1, B2, Bk1, u3, n0 + 1);
                w0 = v0; w1 = v1; w2 = v2; w3 = v3;
            }
            mrg2(A1, A2, Ak1, 1); mrg2(A1, A2, Ak1, 2);
            mrg2(B1, B2, Bk1, 1); mrg2(B1, B2, Bk1, 2);
            if (qid == 0) {
                int rA = rb + gid, rB = rA + 8;
                float epsA = __fmaf_rn(sqrtf(sZn[rA]), *sC, 1e-4f);
                float epsB = __fmaf_rn(sqrtf(sZn[rB]), *sC, 1e-4f);
                sWin[rA] = Ak1;
                sWin[rB] = Bk1;
                if (A2 - A1 < epsA) sLF[atomicAdd(sCnt, 1)] = rA;
                if (B2 - B1 < epsB) sLF[atomicAdd(sCnt, 1)] = rB;
            }
        }
        __syncthreads();

        // ---- exact fp32 full refine of flagged rows (gmem cb, L2-hot) ----
        for (int fi = wid; fi < sCnt[0]; fi += 8) {
            const int row = sLF[fi];
            const float zn = sZn[row];
            const float* zr = sZ + row * 65;
            unsigned long long key = 0xffffffffffffffffULL;
#pragma unroll 1
            for (int kk = 0; kk < 16; kk++) {
                int k = kk * 32 + lid;
                const float4* e4 = (const float4*)(cb + k * D_DIM);
                float aE = 0.0f, aO = 0.0f;
#pragma unroll
                for (int j = 0; j < 16; j++) {
                    float4 e = __ldg(e4 + j);
                    aE = __fmaf_rn(zr[4 * j],     e.x, aE);
                    aO = __fmaf_rn(zr[4 * j + 1], e.y, aO);
                    aE = __fmaf_rn(zr[4 * j + 2], e.z, aE);
                    aO = __fmaf_rn(zr[4 * j + 3], e.w, aO);
                }
                float s = __fadd_rn(__fadd_rn(zn, sNrm[k]),
                                    __fmul_rn(-2.0f, __fadd_rn(aE, aO)));
                unsigned long long c =
                    ((unsigned long long)__float_as_uint(s) << 32) | (unsigned)k;
                if (c < key) key = c;
            }
#pragma unroll
            for (int off = 16; off > 0; off >>= 1) {
                unsigned long long o = __shfl_xor_sync(0xffffffffu, key, off);
                if (o < key) key = o;
            }
            if (lid == 0) sWin[row] = (int)(key & 0xffffffffu);
        }
        __syncthreads();

        // ---- fused gather write from gmem codebook (L2-hot) ----
        {
            const float4* cb4 = (const float4*)cb;
            float4* out4 = (float4*)out + (size_t)tile * 2048;
#pragma unroll
            for (int m = 0; m < 8; m++) {
                int q = tid + THREADS * m;
                out4[q] = cb4[sWin[q >> 4] * 16 + (q & 15)];
            }
            if (fidx && tid < TILE_M)
                fidx[tile * TILE_M + tid] = (float)sWin[tid];
        }
    }
}

extern "C" void kernel_launch(void* const* d_in, const int* in_sizes, int n_in,
                              void* d_out, int out_size) {
    const float* z_e = (const float*)d_in[0];
    const float* cb  = (const float*)d_in[1];
    if (n_in >= 2 && in_sizes[0] == K_CODES * D_DIM) {
        const float* t = z_e; z_e = cb; cb = t;
    }
    float* out = (float*)d_out;
    float* fidx = (out_size > ZQ_ELEMS) ? out + ZQ_ELEMS : nullptr;

    cudaFuncSetAttribute(vq_mma, cudaFuncAttributeMaxDynamicSharedMemorySize,
                         SMEM_BYTES);
    vq_mma<<<GRID, THREADS, SMEM_BYTES>>>(z_e, cb, out, fidx);
}

// round 10
// speedup vs baseline: 5.0841x; 5.0841x over previous
#include <cuda_runtime.h>
#include <cstdint>

// R9 = R5's validated kernel scaled to 512 threads / 16 warps / TILE_M=256
// (4 warps per SMSP instead of 2; inner loop unchanged from the 131.6us R5).

#define N_ROWS   131072
#define K_CODES  512
#define D_DIM    64
#define ZQ_ELEMS (N_ROWS * D_DIM)
#define TILE_M   256
#define NTILES   (N_ROWS / TILE_M)   // 512
#define THREADS  512
#define GRID     152
#define EPS      2e-4f
#define PCB      68                  // padded floats per code row (bank-safe)
#define PZ       65                  // padded floats per z row

// smem float offsets
#define O_CB   0                      // 512*68 = 34816
#define O_Z    34816                  // 256*65 = 16640
#define O_NRM  51456                  // 512
#define O_ZN   51968                  // 256
#define O_WIN  52224                  // 256 (int)
#define O_LIST 52480                  // 256 (int)
#define O_CNT  52736                  // 1 (int)
#define SMEM_F 52740
#define SMEM_BYTES (SMEM_F * 4)       // 210960

__device__ __forceinline__ uint32_t f2tf32(float f) {
    uint32_t r;
    asm("cvt.rna.tf32.f32 %0, %1;" : "=r"(r) : "f"(f));
    return r;
}
__device__ __forceinline__ void mma_tf32(float& c0, float& c1, float& c2, float& c3,
                                         uint32_t a0, uint32_t a1, uint32_t a2, uint32_t a3,
                                         uint32_t b0, uint32_t b1) {
    asm volatile(
        "mma.sync.aligned.m16n8k8.row.col.f32.tf32.tf32.f32 "
        "{%0,%1,%2,%3}, {%4,%5,%6,%7}, {%8,%9}, {%0,%1,%2,%3};"
        : "+f"(c0), "+f"(c1), "+f"(c2), "+f"(c3)
        : "r"(a0), "r"(a1), "r"(a2), "r"(a3), "r"(b0), "r"(b1));
}

__global__ void __launch_bounds__(THREADS, 1)
vq_mma(const float* __restrict__ z_e, const float* __restrict__ cb,
       float* __restrict__ out, float* __restrict__ fidx) {
    extern __shared__ float sh[];
    float* sCB  = sh + O_CB;
    float* sZ   = sh + O_Z;
    float* sNrm = sh + O_NRM;
    float* sZn  = sh + O_ZN;
    int*   sWin = (int*)(sh + O_WIN);
    int*   sLst = (int*)(sh + O_LIST);
    int*   sCnt = (int*)(sh + O_CNT);

    const int tid = threadIdx.x, wid = tid >> 5, lid = tid & 31;
    const int qid = lid & 3, gid = lid >> 2;

    // ---- stage exact codebook into padded smem (once) ----
    {
        const float4* src = (const float4*)cb;
#pragma unroll
        for (int i = 0; i < 16; i++) {
            int e = i * THREADS + tid;         // 0..8191 float4s
            int k = e >> 4, j = e & 15;
            *(float4*)(sCB + k * PCB + 4 * j) = src[e];
        }
    }
    __syncthreads();
    // ---- code norms (sequential-d fp32, ref order) ----
    {
        int k = tid;
        if (k < K_CODES) {
            const float* e = sCB + k * PCB;
            float s = 0.0f;
#pragma unroll 8
            for (int d = 0; d < D_DIM; d++)
                s = __fadd_rn(s, __fmul_rn(e[d], e[d]));
            sNrm[k] = s;
        }
    }
    __syncthreads();

    for (int tile = blockIdx.x; tile < NTILES; tile += GRID) {
        __syncthreads();   // protect sZ/sWin reuse across iterations
        {   // stage z tile -> sZ[row][c] (pad 65); 256 rows stay in one batch b
            const int row0 = tile * TILE_M;
            const float4* z4 = (const float4*)(z_e + (long)(row0 >> 12) * 262144
                                               + (row0 & 4095));
#pragma unroll
            for (int m = 0; m < 8; m++) {
                int q = tid + THREADS * m;     // 0..4095
                int c = q >> 6, i4 = q & 63;
                float4 v = z4[c * 1024 + i4];
                int r = i4 * 4;
                sZ[(r + 0) * PZ + c] = v.x;
                sZ[(r + 1) * PZ + c] = v.y;
                sZ[(r + 2) * PZ + c] = v.z;
                sZ[(r + 3) * PZ + c] = v.w;
            }
        }
        if (tid == 0) *sCnt = 0;
        __syncthreads();
        if (tid < TILE_M) {   // ||z||^2, sequential-d
            const float* zr = sZ + tid * PZ;
            float s = 0.0f;
#pragma unroll 8
            for (int d = 0; d < D_DIM; d++)
                s = __fadd_rn(s, __fmul_rn(zr[d], zr[d]));
            sZn[tid] = s;
        }
        __syncthreads();

        // ---- mma + fused argmin: warp handles 16 rows (R5 loop verbatim) ----
        {
            const int rb = wid * 16;
            uint32_t A[8][4];
#pragma unroll
            for (int ks = 0; ks < 8; ks++) {
                const float* r0 = sZ + (rb + gid) * PZ + ks * 8 + qid;
                const float* r1 = r0 + 8 * PZ;
                A[ks][0] = f2tf32(r0[0]);
                A[ks][1] = f2tf32(r1[0]);
                A[ks][2] = f2tf32(r0[4]);
                A[ks][3] = f2tf32(r1[4]);
            }
            float m1a = 3.4e38f, m2a = 3.4e38f, m1b = 3.4e38f, m2b = 3.4e38f;
            int k1a = 0, k1b = 0;
            const float2* nrm2 = (const float2*)sNrm;
#pragma unroll 1
            for (int nt = 0; nt < 64; nt++) {
                const float* bp = sCB + (nt * 8 + gid) * PCB + qid;
                float c0 = 0, c1 = 0, c2 = 0, c3 = 0;      // even ks chain
                float d0 = 0, d1 = 0, d2 = 0, d3 = 0;      // odd ks chain
#pragma unroll
                for (int ks = 0; ks < 8; ks += 2) {
                    uint32_t b0 = f2tf32(bp[ks * 8]);
                    uint32_t b1 = f2tf32(bp[ks * 8 + 4]);
                    uint32_t b2 = f2tf32(bp[ks * 8 + 8]);
                    uint32_t b3 = f2tf32(bp[ks * 8 + 12]);
                    mma_tf32(c0, c1, c2, c3, A[ks][0], A[ks][1], A[ks][2], A[ks][3], b0, b1);
                    mma_tf32(d0, d1, d2, d3, A[ks + 1][0], A[ks + 1][1], A[ks + 1][2], A[ks + 1][3], b2, b3);
                }
                float2 nk = nrm2[nt * 4 + qid];
                int n0 = nt * 8 + 2 * qid;
                float u;
                u = __fmaf_rn(-2.0f, c0 + d0, nk.x);
                { bool p = u < m1a; m2a = p ? m1a : fminf(m2a, u); m1a = p ? u : m1a; k1a = p ? n0 : k1a; }
                u = __fmaf_rn(-2.0f, c1 + d1, nk.y);
                { bool p = u < m1a; m2a = p ? m1a : fminf(m2a, u); m1a = p ? u : m1a; k1a = p ? n0 + 1 : k1a; }
                u = __fmaf_rn(-2.0f, c2 + d2, nk.x);
                { bool p = u < m1b; m2b = p ? m1b : fminf(m2b, u); m1b = p ? u : m1b; k1b = p ? n0 : k1b; }
                u = __fmaf_rn(-2.0f, c3 + d3, nk.y);
                { bool p = u < m1b; m2b = p ? m1b : fminf(m2b, u); m1b = p ? u : m1b; k1b = p ? n0 + 1 : k1b; }
            }
            // merge across the 4 lanes holding this row's columns
#pragma unroll
            for (int off = 1; off <= 2; off <<= 1) {
                float om1 = __shfl_xor_sync(0xffffffffu, m1a, off);
                float om2 = __shfl_xor_sync(0xffffffffu, m2a, off);
                int   ok1 = __shfl_xor_sync(0xffffffffu, k1a, off);
                float nm2 = fminf(fmaxf(m1a, om1), fminf(m2a, om2));
                if (om1 < m1a || (om1 == m1a && ok1 < k1a)) { m1a = om1; k1a = ok1; }
                m2a = nm2;
                om1 = __shfl_xor_sync(0xffffffffu, m1b, off);
                om2 = __shfl_xor_sync(0xffffffffu, m2b, off);
                ok1 = __shfl_xor_sync(0xffffffffu, k1b, off);
                nm2 = fminf(fmaxf(m1b, om1), fminf(m2b, om2));
                if (om1 < m1b || (om1 == m1b && ok1 < k1b)) { m1b = om1; k1b = ok1; }
                m2b = nm2;
            }
            if (qid == 0) {
                int rA = rb + gid, rB = rA + 8;
                sWin[rA] = k1a;
                sWin[rB] = k1b;
                if (m2a - m1a < EPS) sLst[atomicAdd(sCnt, 1)] = rA;
                if (m2b - m1b < EPS) sLst[atomicAdd(sCnt, 1)] = rB;
            }
        }
        __syncthreads();

        // ---- exact fp32 refine of flagged rows (one warp per row) ----
        {
            const int cnt = *sCnt;
            for (int fi = wid; fi < cnt; fi += 16) {
                const int row = sLst[fi];
                const float zn = sZn[row];
                const float* zr = sZ + row * PZ;
                unsigned long long key = 0xffffffffffffffffULL;
#pragma unroll 1
                for (int kk = 0; kk < 16; kk++) {
                    int k = kk * 32 + lid;
                    const float4* e4 = (const float4*)(sCB + k * PCB);
                    float aE = 0.0f, aO = 0.0f;
#pragma unroll
                    for (int j = 0; j < 16; j++) {
                        float4 e = e4[j];
                        aE = __fmaf_rn(zr[4 * j],     e.x, aE);
                        aO = __fmaf_rn(zr[4 * j + 1], e.y, aO);
                        aE = __fmaf_rn(zr[4 * j + 2], e.z, aE);
                        aO = __fmaf_rn(zr[4 * j + 3], e.w, aO);
                    }
                    float s = __fadd_rn(__fadd_rn(zn, sNrm[k]),
                                        __fmul_rn(-2.0f, __fadd_rn(aE, aO)));
                    unsigned long long c =
                        ((unsigned long long)__float_as_uint(s) << 32) | (unsigned)k;
                    if (c < key) key = c;   // s > 0 always -> bit order == value order
                }
#pragma unroll
                for (int off = 16; off > 0; off >>= 1) {
                    unsigned long long o = __shfl_xor_sync(0xffffffffu, key, off);
                    if (o < key) key = o;
                }
                if (lid == 0) sWin[row] = (int)(key & 0xffffffffu);
            }
        }
        __syncthreads();

        // ---- fused gather write (+ optional indices) ----
        {
            float4* out4 = (float4*)out + (size_t)tile * (TILE_M * 16);
#pragma unroll
            for (int m = 0; m < 8; m++) {
                int q = tid + THREADS * m;     // 0..4095
                int n = q >> 4, j = q & 15;
                out4[q] = *(const float4*)(sCB + sWin[n] * PCB + 4 * j);
            }
            if (fidx && tid < TILE_M)
                fidx[tile * TILE_M + tid] = (float)sWin[tid];
        }
    }
}

extern "C" void kernel_launch(void* const* d_in, const int* in_sizes, int n_in,
                              void* d_out, int out_size) {
    const float* z_e = (const float*)d_in[0];
    const float* cb  = (const float*)d_in[1];
    if (n_in >= 2 && in_sizes[0] == K_CODES * D_DIM) {
        const float* t = z_e; z_e = cb; cb = t;
    }
    float* out = (float*)d_out;
    float* fidx = (out_size > ZQ_ELEMS) ? out + ZQ_ELEMS : nullptr;

    cudaFuncSetAttribute(vq_mma, cudaFuncAttributeMaxDynamicSharedMemorySize,
                         SMEM_BYTES);
    vq_mma<<<GRID, THREADS, SMEM_BYTES>>>(z_e, cb, out, fidx);
}